// round 14
// baseline (speedup 1.0000x reference)
#include <cuda_runtime.h>

#define S_LEN 256
#define GN 4                   // interpolation grid nodes
#define THREADS 32             // one warp = one batch per block
#define RSTRIDE 36             // floats per eighth-region (32 + 4 pad)

__device__ __forceinline__ float ex2f(float v) {
    float y;
    asm("ex2.approx.ftz.f32 %0, %1;" : "=f"(y) : "f"(v));
    return y;
}

__global__ void __launch_bounds__(THREADS)
pico_transformer_adder_kernel(
    const float* __restrict__ x,
    const float* __restrict__ emb_w,
    const float* __restrict__ emb_b,
    const float* __restrict__ q_w,
    const float* __restrict__ q_b,
    const float* __restrict__ k_w,
    const float* __restrict__ k_b,
    const float* __restrict__ v_w,
    const float* __restrict__ v_b,
    const float* __restrict__ f1_w,
    const float* __restrict__ f1_b,
    const float* __restrict__ f2_w,
    const float* __restrict__ f2_b,
    float* __restrict__ out)
{
    __shared__ __align__(16) float xw[8 * RSTRIDE];   // 8 slices of 32 x values

    const int lane = threadIdx.x;
    const int l8   = lane & 7;
    const int b    = blockIdx.x;

    // ---- FRONT-BATCHED LOADS: every global read issues here (round-11 win) ----
    const float4* xr4 = (const float4*)(x + b * S_LEN);
    const float4 va = xr4[lane * 2];
    const float4 vb = xr4[lane * 2 + 1];

    const float4 ew  = *(const float4*)emb_w;
    const float4 eb  = *(const float4*)emb_b;
    const float4 qb4 = *(const float4*)q_b;
    const float4 vb4 = *(const float4*)v_b;
    float4 qw[4], kw[4], vw[4];
    #pragma unroll
    for (int e = 0; e < 4; ++e) {
        qw[e] = ((const float4*)q_w)[e];
        kw[e] = ((const float4*)k_w)[e];
        vw[e] = ((const float4*)v_w)[e];
    }
    const float4 f1  = ((const float4*)f1_w)[l8];
    const float  f1b = f1_b[l8];
    const float  F   = f2_w[l8];
    const float  F2B = f2_b[0];

    // ---- stage x into slab: lane's 8 values live in slice lane>>2 ----
    const int base = (lane >> 2) * RSTRIDE + (lane & 3) * 8;
    *(float4*)(xw + base)     = va;
    *(float4*)(xw + base + 4) = vb;

    // ---- warp min/max of x ----
    float mx = fmaxf(fmaxf(fmaxf(va.x, va.y), fmaxf(va.z, va.w)),
                     fmaxf(fmaxf(vb.x, vb.y), fmaxf(vb.z, vb.w)));
    float mn = fminf(fminf(fminf(va.x, va.y), fminf(va.z, va.w)),
                     fminf(fminf(vb.x, vb.y), fminf(vb.z, vb.w)));
    #pragma unroll
    for (int o = 16; o; o >>= 1) {
        mx = fmaxf(mx, __shfl_xor_sync(0xffffffffu, mx, o));
        mn = fminf(mn, __shfl_xor_sync(0xffffffffu, mn, o));
    }

    // ---- A, C (gates the grid loop) ----
    const float* qbp = (const float*)&qb4;
    float A = 0.f, C = 0.f;
    #pragma unroll
    for (int e = 0; e < 4; ++e) {
        const float qa = qw[e].x*ew.x + qw[e].y*ew.y + qw[e].z*ew.z + qw[e].w*ew.w;
        const float qc = qw[e].x*eb.x + qw[e].y*eb.y + qw[e].z*eb.z + qw[e].w*eb.w + qbp[e];
        const float ka = kw[e].x*ew.x + kw[e].y*ew.y + kw[e].z*ew.z + kw[e].w*ew.w;
        A = fmaf(qa, ka, A);
        C = fmaf(qc, ka, C);
    }
    A *= 0.5f;   // 1/sqrt(d), d=4
    C *= 0.5f;

    // ---- alpha grid (warp-uniform) ----
    const float LOG2E = 1.4426950408889634f;
    const float alo = (A >= 0.f) ? fmaf(A, mn, C) : fmaf(A, mx, C);
    const float ahi = (A >= 0.f) ? fmaf(A, mx, C) : fmaf(A, mn, C);
    const float hstep = fmaxf((ahi - alo) * (1.0f / (float)(GN - 1)), 1e-30f);

    __syncwarp(0xffffffffu);   // x slab visible to whole warp

    // ---- grid phase: node g = lane/8, slice sl = lane&7, 32 j's per lane ----
    const int g  = lane >> 3;
    const int sl = lane & 7;
    const float ag2 = fmaf((float)g, hstep, alo) * LOG2E;
    const float mg  = fmaxf(ag2 * mx, ag2 * mn);   // max achieved by data

    const float4* xp = (const float4*)(xw + sl * RSTRIDE);

    float s0a = 0.f, s1a = 0.f, s2a = 0.f;
    float s0b = 0.f, s1b = 0.f, s2b = 0.f;
    #pragma unroll
    for (int c = 0; c < 8; c += 2) {
        const float4 v = xp[c];
        const float4 u = xp[c + 1];
        float p, px;
        p = ex2f(fmaf(ag2, v.x, -mg)); px = p*v.x; s0a += p; s1a += px; s2a = fmaf(px, v.x, s2a);
        p = ex2f(fmaf(ag2, v.y, -mg)); px = p*v.y; s0a += p; s1a += px; s2a = fmaf(px, v.y, s2a);
        p = ex2f(fmaf(ag2, v.z, -mg)); px = p*v.z; s0a += p; s1a += px; s2a = fmaf(px, v.z, s2a);
        p = ex2f(fmaf(ag2, v.w, -mg)); px = p*v.w; s0a += p; s1a += px; s2a = fmaf(px, v.w, s2a);
        p = ex2f(fmaf(ag2, u.x, -mg)); px = p*u.x; s0b += p; s1b += px; s2b = fmaf(px, u.x, s2b);
        p = ex2f(fmaf(ag2, u.y, -mg)); px = p*u.y; s0b += p; s1b += px; s2b = fmaf(px, u.y, s2b);
        p = ex2f(fmaf(ag2, u.z, -mg)); px = p*u.z; s0b += p; s1b += px; s2b = fmaf(px, u.z, s2b);
        p = ex2f(fmaf(ag2, u.w, -mg)); px = p*u.w; s0b += p; s1b += px; s2b = fmaf(px, u.w, s2b);
    }
    float s0 = s0a + s0b, s1 = s1a + s1b, s2 = s2a + s2b;
    #pragma unroll
    for (int o = 1; o < 8; o <<= 1) {
        s0 += __shfl_xor_sync(0xffffffffu, s0, o);
        s1 += __shfl_xor_sync(0xffffffffu, s1, o);
        s2 += __shfl_xor_sync(0xffffffffu, s2, o);
    }

    const float inv = __fdividef(1.0f, s0);
    const float mv  = s1 * inv;                          // m(alpha_g), node g in lanes 8g..8g+7
    const float dvh = fmaf(-mv, mv, s2 * inv) * hstep;   // h * m'(alpha_g)

    // ---- Hermite interpolation at this lane's 8 x values; nodes via shfl.idx ----
    const float inv_h = __fdividef(1.0f, hstep);
    const float xr[8] = {va.x, va.y, va.z, va.w, vb.x, vb.y, vb.z, vb.w};
    float psum = 0.f;
    #pragma unroll
    for (int k = 0; k < 8; ++k) {
        const float u  = (fmaf(A, xr[k], C) - alo) * inv_h;
        int g0 = (int)u;
        g0 = max(0, min(g0, GN - 2));
        const float tt = u - (float)g0;
        const int src = g0 << 3;
        const float m0 = __shfl_sync(0xffffffffu, mv,  src);
        const float m1 = __shfl_sync(0xffffffffu, mv,  src + 8);
        const float d0 = __shfl_sync(0xffffffffu, dvh, src);
        const float d1 = __shfl_sync(0xffffffffu, dvh, src + 8);
        const float t2 = tt * tt, t3 = t2 * tt;
        psum += (2.f*t3 - 3.f*t2 + 1.f) * m0
              + (t3 - 2.f*t2 + tt)      * d0
              + (-2.f*t3 + 3.f*t2)      * m1
              + (t3 - t2)               * d1;
    }
    #pragma unroll
    for (int o = 16; o; o >>= 1) psum += __shfl_xor_sync(0xffffffffu, psum, o);
    const float M = psum * (1.0f / (float)S_LEN);

    // ---- epilogue: all data register-resident; pure FMA ----
    float yv = 0.f;
    if (lane < 8) {
        const float* vbp = (const float*)&vb4;
        float vaw[4], vcw[4];
        #pragma unroll
        for (int e = 0; e < 4; ++e) {
            vaw[e] = vw[e].x*ew.x + vw[e].y*ew.y + vw[e].z*ew.z + vw[e].w*ew.w;
            vcw[e] = vw[e].x*eb.x + vw[e].y*eb.y + vw[e].z*eb.z + vw[e].w*eb.w + vbp[e];
        }
        const float P = f1.x*vaw[0] + f1.y*vaw[1] + f1.z*vaw[2] + f1.w*vaw[3];
        const float R = f1.x*vcw[0] + f1.y*vcw[1] + f1.z*vcw[2] + f1.w*vcw[3] + f1b;
        yv = F * fmaxf(fmaf(P, M, R), 0.f);
    }
    yv += __shfl_xor_sync(0xffffffffu, yv, 1);
    yv += __shfl_xor_sync(0xffffffffu, yv, 2);
    yv += __shfl_xor_sync(0xffffffffu, yv, 4);
    if (lane == 0) out[b] = yv + F2B;
}

extern "C" void kernel_launch(void* const* d_in, const int* in_sizes, int n_in,
                              void* d_out, int out_size) {
    const float* x     = (const float*)d_in[0];
    const float* emb_w = (const float*)d_in[1];
    const float* emb_b = (const float*)d_in[2];
    const float* q_w   = (const float*)d_in[3];
    const float* q_b   = (const float*)d_in[4];
    const float* k_w   = (const float*)d_in[5];
    const float* k_b   = (const float*)d_in[6];
    const float* v_w   = (const float*)d_in[7];
    const float* v_b   = (const float*)d_in[8];
    const float* f1_w  = (const float*)d_in[9];
    const float* f1_b  = (const float*)d_in[10];
    const float* f2_w  = (const float*)d_in[11];
    const float* f2_b  = (const float*)d_in[12];

    const int B = in_sizes[0] / S_LEN;

    pico_transformer_adder_kernel<<<B, THREADS>>>(
        x, emb_w, emb_b, q_w, q_b, k_w, k_b, v_w, v_b,
        f1_w, f1_b, f2_w, f2_b, (float*)d_out);
}

// round 15
// speedup vs baseline: 1.0048x; 1.0048x over previous
#include <cuda_runtime.h>

#define S_LEN 256
#define GN 8                   // interpolation grid nodes
#define THREADS 32             // one warp = one batch per block
#define RSTRIDE 68             // floats per quarter-region (64 + 4 pad)

__device__ __forceinline__ float ex2f(float v) {
    float y;
    asm("ex2.approx.ftz.f32 %0, %1;" : "=f"(y) : "f"(v));
    return y;
}

__global__ void __launch_bounds__(THREADS)
pico_transformer_adder_kernel(
    const float* __restrict__ x,
    const float* __restrict__ emb_w,
    const float* __restrict__ emb_b,
    const float* __restrict__ q_w,
    const float* __restrict__ q_b,
    const float* __restrict__ k_w,
    const float* __restrict__ k_b,
    const float* __restrict__ v_w,
    const float* __restrict__ v_b,
    const float* __restrict__ f1_w,
    const float* __restrict__ f1_b,
    const float* __restrict__ f2_w,
    const float* __restrict__ f2_b,
    float* __restrict__ out)
{
    __shared__ __align__(16) float xw[4 * RSTRIDE];   // x values only

    const int lane = threadIdx.x;
    const int l8   = lane & 7;
    const int b    = blockIdx.x;

    // ---- FRONT-BATCHED LOADS: every global read issues here so LDG latency
    // overlaps the min/max + grid phase instead of being exposed on the tail.
    const float4* xr4 = (const float4*)(x + b * S_LEN);
    const float4 va = xr4[lane * 2];
    const float4 vb = xr4[lane * 2 + 1];

    const float4 ew  = *(const float4*)emb_w;
    const float4 eb  = *(const float4*)emb_b;
    const float4 qb4 = *(const float4*)q_b;
    const float4 vb4 = *(const float4*)v_b;
    float4 qw[4], kw[4], vw[4];
    #pragma unroll
    for (int e = 0; e < 4; ++e) {
        qw[e] = ((const float4*)q_w)[e];
        kw[e] = ((const float4*)k_w)[e];
        vw[e] = ((const float4*)v_w)[e];
    }
    const float4 f1  = ((const float4*)f1_w)[l8];   // row lane&7 (unconditional)
    const float  f1b = f1_b[l8];
    const float  F   = f2_w[l8];
    const float  F2B = f2_b[0];

    // ---- stage x into slab: quarter r = lane>>3 at r*RSTRIDE ----
    const int base = (lane >> 3) * RSTRIDE + l8 * 8;
    *(float4*)(xw + base)     = va;
    *(float4*)(xw + base + 4) = vb;

    // ---- warp min/max of x ----
    float mx = fmaxf(fmaxf(fmaxf(va.x, va.y), fmaxf(va.z, va.w)),
                     fmaxf(fmaxf(vb.x, vb.y), fmaxf(vb.z, vb.w)));
    float mn = fminf(fminf(fminf(va.x, va.y), fminf(va.z, va.w)),
                     fminf(fminf(vb.x, vb.y), fminf(vb.z, vb.w)));
    #pragma unroll
    for (int o = 16; o; o >>= 1) {
        mx = fmaxf(mx, __shfl_xor_sync(0xffffffffu, mx, o));
        mn = fminf(mn, __shfl_xor_sync(0xffffffffu, mn, o));
    }

    // ---- A, C (gates the grid loop) ----
    const float* qbp = (const float*)&qb4;
    float A = 0.f, C = 0.f;
    #pragma unroll
    for (int e = 0; e < 4; ++e) {
        const float qa = qw[e].x*ew.x + qw[e].y*ew.y + qw[e].z*ew.z + qw[e].w*ew.w;
        const float qc = qw[e].x*eb.x + qw[e].y*eb.y + qw[e].z*eb.z + qw[e].w*eb.w + qbp[e];
        const float ka = kw[e].x*ew.x + kw[e].y*ew.y + kw[e].z*ew.z + kw[e].w*ew.w;
        A = fmaf(qa, ka, A);
        C = fmaf(qc, ka, C);
    }
    A *= 0.5f;   // 1/sqrt(d), d=4
    C *= 0.5f;

    // ---- alpha grid (warp-uniform) ----
    const float LOG2E = 1.4426950408889634f;
    const float alo = (A >= 0.f) ? fmaf(A, mn, C) : fmaf(A, mx, C);
    const float ahi = (A >= 0.f) ? fmaf(A, mx, C) : fmaf(A, mn, C);
    const float hstep = fmaxf((ahi - alo) * (1.0f / (float)(GN - 1)), 1e-30f);

    __syncwarp(0xffffffffu);   // x slab visible to whole warp

    // ---- grid phase: node g = lane/4, quarter qd = lane&3, 64 j's per lane ----
    const int g  = lane >> 2;
    const int qd = lane & 3;
    const float ag2 = fmaf((float)g, hstep, alo) * LOG2E;
    const float mg  = fmaxf(ag2 * mx, ag2 * mn);   // max achieved by data

    const float4* xp = (const float4*)(xw + qd * RSTRIDE);

    float s0a = 0.f, s1a = 0.f, s2a = 0.f;
    float s0b = 0.f, s1b = 0.f, s2b = 0.f;
    #pragma unroll 4
    for (int c = 0; c < 16; c += 2) {
        const float4 v = xp[c];
        const float4 u = xp[c + 1];
        float p, px;
        p = ex2f(fmaf(ag2, v.x, -mg)); px = p*v.x; s0a += p; s1a += px; s2a = fmaf(px, v.x, s2a);
        p = ex2f(fmaf(ag2, v.y, -mg)); px = p*v.y; s0a += p; s1a += px; s2a = fmaf(px, v.y, s2a);
        p = ex2f(fmaf(ag2, v.z, -mg)); px = p*v.z; s0a += p; s1a += px; s2a = fmaf(px, v.z, s2a);
        p = ex2f(fmaf(ag2, v.w, -mg)); px = p*v.w; s0a += p; s1a += px; s2a = fmaf(px, v.w, s2a);
        p = ex2f(fmaf(ag2, u.x, -mg)); px = p*u.x; s0b += p; s1b += px; s2b = fmaf(px, u.x, s2b);
        p = ex2f(fmaf(ag2, u.y, -mg)); px = p*u.y; s0b += p; s1b += px; s2b = fmaf(px, u.y, s2b);
        p = ex2f(fmaf(ag2, u.z, -mg)); px = p*u.z; s0b += p; s1b += px; s2b = fmaf(px, u.z, s2b);
        p = ex2f(fmaf(ag2, u.w, -mg)); px = p*u.w; s0b += p; s1b += px; s2b = fmaf(px, u.w, s2b);
    }
    float s0 = s0a + s0b, s1 = s1a + s1b, s2 = s2a + s2b;
    #pragma unroll
    for (int o = 1; o < 4; o <<= 1) {
        s0 += __shfl_xor_sync(0xffffffffu, s0, o);
        s1 += __shfl_xor_sync(0xffffffffu, s1, o);
        s2 += __shfl_xor_sync(0xffffffffu, s2, o);
    }

    const float inv = __fdividef(1.0f, s0);
    const float mv  = s1 * inv;                          // m(alpha_g), node g in lanes 4g..4g+3
    const float dvh = fmaf(-mv, mv, s2 * inv) * hstep;   // h * m'(alpha_g)

    // ---- Hermite interpolation at this lane's 8 x values; nodes via shfl.idx ----
    const float inv_h = __fdividef(1.0f, hstep);
    const float xr[8] = {va.x, va.y, va.z, va.w, vb.x, vb.y, vb.z, vb.w};
    float psum = 0.f;
    #pragma unroll
    for (int k = 0; k < 8; ++k) {
        const float u  = (fmaf(A, xr[k], C) - alo) * inv_h;
        int g0 = (int)u;
        g0 = max(0, min(g0, GN - 2));
        const float tt = u - (float)g0;
        const int src = g0 << 2;
        const float m0 = __shfl_sync(0xffffffffu, mv,  src);
        const float m1 = __shfl_sync(0xffffffffu, mv,  src + 4);
        const float d0 = __shfl_sync(0xffffffffu, dvh, src);
        const float d1 = __shfl_sync(0xffffffffu, dvh, src + 4);
        const float t2 = tt * tt, t3 = t2 * tt;
        psum += (2.f*t3 - 3.f*t2 + 1.f) * m0
              + (t3 - 2.f*t2 + tt)      * d0
              + (-2.f*t3 + 3.f*t2)      * m1
              + (t3 - t2)               * d1;
    }
    #pragma unroll
    for (int o = 16; o; o >>= 1) psum += __shfl_xor_sync(0xffffffffu, psum, o);
    const float M = psum * (1.0f / (float)S_LEN);

    // ---- epilogue: all data register-resident; pure FMA ----
    float yv = 0.f;
    if (lane < 8) {
        const float* vbp = (const float*)&vb4;
        float vaw[4], vcw[4];
        #pragma unroll
        for (int e = 0; e < 4; ++e) {
            vaw[e] = vw[e].x*ew.x + vw[e].y*ew.y + vw[e].z*ew.z + vw[e].w*ew.w;
            vcw[e] = vw[e].x*eb.x + vw[e].y*eb.y + vw[e].z*eb.z + vw[e].w*eb.w + vbp[e];
        }
        const float P = f1.x*vaw[0] + f1.y*vaw[1] + f1.z*vaw[2] + f1.w*vaw[3];
        const float R = f1.x*vcw[0] + f1.y*vcw[1] + f1.z*vcw[2] + f1.w*vcw[3] + f1b;
        yv = F * fmaxf(fmaf(P, M, R), 0.f);
    }
    yv += __shfl_xor_sync(0xffffffffu, yv, 1);
    yv += __shfl_xor_sync(0xffffffffu, yv, 2);
    yv += __shfl_xor_sync(0xffffffffu, yv, 4);
    if (lane == 0) out[b] = yv + F2B;
}

extern "C" void kernel_launch(void* const* d_in, const int* in_sizes, int n_in,
                              void* d_out, int out_size) {
    const float* x     = (const float*)d_in[0];
    const float* emb_w = (const float*)d_in[1];
    const float* emb_b = (const float*)d_in[2];
    const float* q_w   = (const float*)d_in[3];
    const float* q_b   = (const float*)d_in[4];
    const float* k_w   = (const float*)d_in[5];
    const float* k_b   = (const float*)d_in[6];
    const float* v_w   = (const float*)d_in[7];
    const float* v_b   = (const float*)d_in[8];
    const float* f1_w  = (const float*)d_in[9];
    const float* f1_b  = (const float*)d_in[10];
    const float* f2_w  = (const float*)d_in[11];
    const float* f2_b  = (const float*)d_in[12];

    const int B = in_sizes[0] / S_LEN;

    pico_transformer_adder_kernel<<<B, THREADS>>>(
        x, emb_w, emb_b, q_w, q_b, k_w, k_b, v_w, v_b,
        f1_w, f1_b, f2_w, f2_b, (float*)d_out);
}